// round 5
// baseline (speedup 1.0000x reference)
#include <cuda_runtime.h>

#define BATCH 262144
#define NBLOCKS (BATCH / 128)

static __device__ double g_acc = 0.0;
static __device__ unsigned int g_cnt = 0;

// Monotone key equivalent to atan2f(y, x) ordering over (-pi, pi].
__device__ __forceinline__ float pangle(float x, float y) {
  float a = fabsf(x) + fabsf(y);
  float r = (a == 0.0f) ? 1.0f : __fdividef(x, a);
  return (y >= 0.0f) ? (1.0f - r) : (r - 1.0f);
}

// In-place sort of 8 (ang, x, y) triples by ang via Batcher odd-even mergesort
// (19 comparators). Inlined with constant indices -> stays in registers.
__device__ __forceinline__ void sort8(float* ang, float* px, float* py) {
#define CSW(i, j)                                                   \
  do {                                                              \
    bool sw_ = ang[i] > ang[j];                                     \
    float ta = ang[i], tx = px[i], ty = py[i];                      \
    ang[i] = sw_ ? ang[j] : ang[i];                                 \
    px[i] = sw_ ? px[j] : px[i];                                    \
    py[i] = sw_ ? py[j] : py[i];                                    \
    ang[j] = sw_ ? ta : ang[j];                                     \
    px[j] = sw_ ? tx : px[j];                                       \
    py[j] = sw_ ? ty : py[j];                                       \
  } while (0)
  CSW(0, 1); CSW(2, 3); CSW(4, 5); CSW(6, 7);
  CSW(0, 2); CSW(1, 3); CSW(4, 6); CSW(5, 7);
  CSW(1, 2); CSW(5, 6);
  CSW(0, 4); CSW(1, 5); CSW(2, 6); CSW(3, 7);
  CSW(2, 4); CSW(3, 5);
  CSW(1, 2); CSW(3, 4); CSW(5, 6);
#undef CSW
}

__global__ void __launch_bounds__(128) ciou_main_kernel(
    const float* __restrict__ A, const float* __restrict__ Bm,
    float* __restrict__ out) {
  int i = blockIdx.x * blockDim.x + threadIdx.x;

  // ---------------- load originals (kept for hull) -------------------------
  float oxa[8], oya[8], oxb[8], oyb[8];
  {
    const float4* a4 = reinterpret_cast<const float4*>(A) + (size_t)i * 4;
    const float4* b4 = reinterpret_cast<const float4*>(Bm) + (size_t)i * 4;
#pragma unroll
    for (int k = 0; k < 4; k++) {
      float4 q = a4[k];
      oxa[2 * k] = q.x; oya[2 * k] = q.y; oxa[2 * k + 1] = q.z; oya[2 * k + 1] = q.w;
    }
#pragma unroll
    for (int k = 0; k < 4; k++) {
      float4 q = b4[k];
      oxb[2 * k] = q.x; oyb[2 * k] = q.y; oxb[2 * k + 1] = q.z; oyb[2 * k + 1] = q.w;
    }
  }

  // ---------------- sort_poly (sorting network, pseudoangle keys) ----------
  float sax[8], say[8], sbx[8], sby[8];
  {
    float cx = 0.f, cy = 0.f;
#pragma unroll
    for (int k = 0; k < 8; k++) { cx += oxa[k]; cy += oya[k]; }
    cx *= 0.125f; cy *= 0.125f;
    float ang[8];
#pragma unroll
    for (int k = 0; k < 8; k++) {
      ang[k] = pangle(oxa[k] - cx, oya[k] - cy);
      sax[k] = oxa[k]; say[k] = oya[k];
    }
    sort8(ang, sax, say);
  }
  {
    float cx = 0.f, cy = 0.f;
#pragma unroll
    for (int k = 0; k < 8; k++) { cx += oxb[k]; cy += oyb[k]; }
    cx *= 0.125f; cy *= 0.125f;
    float ang[8];
#pragma unroll
    for (int k = 0; k < 8; k++) {
      ang[k] = pangle(oxb[k] - cx, oyb[k] - cy);
      sbx[k] = oxb[k]; sby[k] = oyb[k];
    }
    sort8(ang, sbx, sby);
  }

  // ---------------- edges + shoelace areas ---------------------------------
  float eax[8], eay[8], ebx[8], eby[8];
#pragma unroll
  for (int k = 0; k < 8; k++) {
    eax[k] = sax[(k + 1) & 7] - sax[k];
    eay[k] = say[(k + 1) & 7] - say[k];
    ebx[k] = sbx[(k + 1) & 7] - sbx[k];
    eby[k] = sby[(k + 1) & 7] - sby[k];
  }
  float area_a = 0.f, area_b = 0.f;
#pragma unroll
  for (int k = 0; k < 8; k++) {
    area_a += sax[k] * say[(k + 1) & 7] - say[k] * sax[(k + 1) & 7];
    area_b += sbx[k] * sby[(k + 1) & 7] - sby[k] * sbx[(k + 1) & 7];
  }
  area_a *= 0.5f; area_b *= 0.5f;

  // ---------------- candidates: inside vertices + edge intersections -------
  float cxl[40], cyl[40], cal[40];
  int cnt = 0;
  float sumx = 0.f, sumy = 0.f;

#pragma unroll
  for (int j = 0; j < 8; j++) {
    bool all = true;
#pragma unroll
    for (int k = 0; k < 8; k++) {
      float wx = sax[j] - sbx[k], wy = say[j] - sby[k];
      float cr = ebx[k] * wy - eby[k] * wx;
      all = all && (cr >= -1e-6f);
    }
    if (all) { cxl[cnt] = sax[j]; cyl[cnt] = say[j]; sumx += sax[j]; sumy += say[j]; cnt++; }
  }
#pragma unroll
  for (int j = 0; j < 8; j++) {
    bool all = true;
#pragma unroll
    for (int k = 0; k < 8; k++) {
      float wx = sbx[j] - sax[k], wy = sby[j] - say[k];
      float cr = eax[k] * wy - eay[k] * wx;
      all = all && (cr >= -1e-6f);
    }
    if (all) { cxl[cnt] = sbx[j]; cyl[cnt] = sby[j]; sumx += sbx[j]; sumy += sby[j]; cnt++; }
  }
  // division-free accept test; divide only for accepted pairs (~8 of 64)
#pragma unroll
  for (int ii = 0; ii < 8; ii++) {
#pragma unroll
    for (int jj = 0; jj < 8; jj++) {
      float denom = eax[ii] * eby[jj] - eay[ii] * ebx[jj];
      float ad = fabsf(denom);
      float rx = sbx[jj] - sax[ii], ry = sby[jj] - say[ii];
      float nt = rx * eby[jj] - ry * ebx[jj];
      float nu = rx * eay[ii] - ry * eax[ii];
      bool neg = denom < 0.0f;
      float ntA = neg ? -nt : nt;
      float nuA = neg ? -nu : nu;
      bool ok = (ad >= 1e-9f) && (ntA >= 0.0f) && (ntA <= ad) &&
                (nuA >= 0.0f) && (nuA <= ad);
      if (ok) {
        float t = __fdividef(nt, denom);
        float px = sax[ii] + t * eax[ii];
        float py = say[ii] + t * eay[ii];
        cxl[cnt] = px; cyl[cnt] = py; sumx += px; sumy += py; cnt++;
      }
    }
  }

  // ---------------- intersection area: pseudoangle sort about centroid -----
  float inter = 0.0f;
  {
    float cntf = fmaxf((float)cnt, 1.0f);
    float ctrx = sumx / cntf, ctry = sumy / cntf;
    for (int t0 = 0; t0 < cnt; t0++)
      cal[t0] = pangle(cxl[t0] - ctrx, cyl[t0] - ctry);
    for (int s = 1; s < cnt; s++) {
      float ka = cal[s], kx = cxl[s], ky = cyl[s];
      int t = s - 1;
      while (t >= 0 && cal[t] > ka) {
        cal[t + 1] = cal[t]; cxl[t + 1] = cxl[t]; cyl[t + 1] = cyl[t];
        t--;
      }
      cal[t + 1] = ka; cxl[t + 1] = kx; cyl[t + 1] = ky;
    }
    float sh = 0.f;
    for (int t0 = 0; t0 < cnt; t0++) {
      int t1 = (t0 + 1 == cnt) ? 0 : t0 + 1;
      sh += cxl[t0] * cyl[t1] - cyl[t0] * cxl[t1];
    }
    inter = (cnt >= 3) ? fmaxf(0.5f * sh, 0.0f) : 0.0f;
  }

  float uni = area_a + area_b - inter;
  float iou = inter / uni;

  // ---------------- convex hull: cross-product Jarvis, chained tournament --
  float ch;
  {
    int start = 0;
    float cpx = oxa[0], cpy = oya[0];
#pragma unroll
    for (int k = 1; k < 16; k++) {
      float pxk = (k < 8) ? oxa[k] : oxb[k - 8];
      float pyk = (k < 8) ? oya[k] : oyb[k - 8];
      bool better = (pyk < cpy) || ((pyk == cpy) && (pxk < cpx));
      if (better) { start = k; cpx = pxk; cpy = pyk; }
    }
    float acc = 0.0f;
    for (int it = 0; it < 16; it++) {
      // 4 independent sequential chains of 4 candidates each
      float bvx[4], bvy[4], bd2[4], bpx[4], bpy[4];
      int bidx[4]; bool bval[4];
#pragma unroll
      for (int c = 0; c < 4; c++) {
        bval[c] = false; bvx[c] = 0.f; bvy[c] = 0.f; bd2[c] = 0.f;
        bpx[c] = 0.f; bpy[c] = 0.f; bidx[c] = 0;
#pragma unroll
        for (int t = 0; t < 4; t++) {
          int k = c * 4 + t;
          float pxk = (k < 8) ? oxa[k] : oxb[k - 8];
          float pyk = (k < 8) ? oya[k] : oyb[k - 8];
          float vx = pxk - cpx, vy = pyk - cpy;
          float d2 = vx * vx + vy * vy;
          bool valid = d2 >= 1e-16f;
          float cr = bvx[c] * vy - bvy[c] * vx;
          bool take = valid &&
                      (!bval[c] || (cr < 0.0f) || (cr == 0.0f && d2 > bd2[c]));
          bvx[c] = take ? vx : bvx[c];
          bvy[c] = take ? vy : bvy[c];
          bd2[c] = take ? d2 : bd2[c];
          bpx[c] = take ? pxk : bpx[c];
          bpy[c] = take ? pyk : bpy[c];
          bidx[c] = take ? k : bidx[c];
          bval[c] = bval[c] || take;
        }
      }
      // tree combine: 0<-1, 2<-3, 0<-2
#pragma unroll
      for (int st = 0; st < 3; st++) {
        int a = (st == 2) ? 0 : (st * 2);
        int b = (st == 2) ? 2 : (st * 2 + 1);
        float cr = bvx[a] * bvy[b] - bvy[a] * bvx[b];
        bool take = bval[b] &&
                    (!bval[a] || (cr < 0.0f) || (cr == 0.0f && bd2[b] > bd2[a]));
        bvx[a] = take ? bvx[b] : bvx[a];
        bvy[a] = take ? bvy[b] : bvy[a];
        bd2[a] = take ? bd2[b] : bd2[a];
        bpx[a] = take ? bpx[b] : bpx[a];
        bpy[a] = take ? bpy[b] : bpy[a];
        bidx[a] = take ? bidx[b] : bidx[a];
        bval[a] = bval[a] || bval[b];
      }
      acc += cpx * bpy[0] - cpy * bpx[0];
      cpx = bpx[0]; cpy = bpy[0];
      if (bidx[0] == start) break;
    }
    ch = 0.5f * acc;
  }

  float ciou_v = iou - (ch - uni) / ch;

  // ---------------- mean reduction (double, single-kernel finalize) --------
  double v = (double)ciou_v;
#pragma unroll
  for (int o = 16; o > 0; o >>= 1) v += __shfl_down_sync(0xFFFFFFFFu, v, o);
  __shared__ double smem[4];
  int lane = threadIdx.x & 31;
  int wid = threadIdx.x >> 5;
  if (lane == 0) smem[wid] = v;
  __syncthreads();
  if (threadIdx.x == 0) {
    double s = smem[0] + smem[1] + smem[2] + smem[3];
    atomicAdd(&g_acc, s);
    __threadfence();
    unsigned int old = atomicAdd(&g_cnt, 1u);
    if (old == (unsigned int)(NBLOCKS - 1)) {
      double total = atomicAdd(&g_acc, 0.0);
      out[0] = (float)(total * (1.0 / (double)BATCH));
      g_acc = 0.0;
      g_cnt = 0u;
    }
  }
}

extern "C" void kernel_launch(void* const* d_in, const int* in_sizes, int n_in,
                              void* d_out, int out_size) {
  const float* a = (const float*)d_in[0];
  const float* b = (const float*)d_in[1];
  float* out = (float*)d_out;
  ciou_main_kernel<<<NBLOCKS, 128>>>(a, b, out);
}

// round 7
// speedup vs baseline: 1.2300x; 1.2300x over previous
#include <cuda_runtime.h>

#define BATCH 262144
#define NBLOCKS (BATCH / 128)

static __device__ double g_acc = 0.0;
static __device__ unsigned int g_cnt = 0;

// Monotone key equivalent to atan2f(y, x) ordering over (-pi, pi].
__device__ __forceinline__ float pangle(float x, float y) {
  float a = fabsf(x) + fabsf(y);
  float r = (a == 0.0f) ? 1.0f : __fdividef(x, a);
  return (y >= 0.0f) ? (1.0f - r) : (r - 1.0f);
}

// Monotone key equivalent to mod(atan2f(c, d), 2pi) ordering over [0, 2pi).
__device__ __forceinline__ float pangle2pi(float c, float d) {
  float a = fabsf(c) + fabsf(d);
  float r = (a == 0.0f) ? 1.0f : __fdividef(d, a);
  return (c >= 0.0f) ? (1.0f - r) : (3.0f + r);
}

__global__ void __launch_bounds__(128, 3) ciou_main_kernel(
    const float* __restrict__ A, const float* __restrict__ Bm,
    float* __restrict__ out) {
  int i = blockIdx.x * blockDim.x + threadIdx.x;
  const float INF_F = __int_as_float(0x7f800000);
  const float4* a4 = reinterpret_cast<const float4*>(A) + (size_t)i * 4;
  const float4* b4 = reinterpret_cast<const float4*>(Bm) + (size_t)i * 4;

  // ---------------- sort_poly (stable rank sort, pseudoangle keys) ---------
  // Load each polygon, sort it, and let the raw copy die (hull reloads later)
  float sax[8], say[8], sbx[8], sby[8];
  {
    float ox[8], oy[8];
#pragma unroll
    for (int k = 0; k < 4; k++) {
      float4 q = a4[k];
      ox[2 * k] = q.x; oy[2 * k] = q.y; ox[2 * k + 1] = q.z; oy[2 * k + 1] = q.w;
    }
    float cx = 0.f, cy = 0.f;
#pragma unroll
    for (int k = 0; k < 8; k++) { cx += ox[k]; cy += oy[k]; }
    cx *= 0.125f; cy *= 0.125f;
    float ang[8];
#pragma unroll
    for (int k = 0; k < 8; k++) ang[k] = pangle(ox[k] - cx, oy[k] - cy);
    int rk[8];
#pragma unroll
    for (int j = 0; j < 8; j++) {
      int r = 0;
#pragma unroll
      for (int k = 0; k < 8; k++)
        r += (int)((ang[k] < ang[j]) || ((ang[k] == ang[j]) && (k < j)));
      rk[j] = r;
    }
#pragma unroll
    for (int s = 0; s < 8; s++) {
      float vx = 0.f, vy = 0.f;
#pragma unroll
      for (int j = 0; j < 8; j++) {
        bool sel = (rk[j] == s);
        vx = sel ? ox[j] : vx;
        vy = sel ? oy[j] : vy;
      }
      sax[s] = vx; say[s] = vy;
    }
  }
  {
    float ox[8], oy[8];
#pragma unroll
    for (int k = 0; k < 4; k++) {
      float4 q = b4[k];
      ox[2 * k] = q.x; oy[2 * k] = q.y; ox[2 * k + 1] = q.z; oy[2 * k + 1] = q.w;
    }
    float cx = 0.f, cy = 0.f;
#pragma unroll
    for (int k = 0; k < 8; k++) { cx += ox[k]; cy += oy[k]; }
    cx *= 0.125f; cy *= 0.125f;
    float ang[8];
#pragma unroll
    for (int k = 0; k < 8; k++) ang[k] = pangle(ox[k] - cx, oy[k] - cy);
    int rk[8];
#pragma unroll
    for (int j = 0; j < 8; j++) {
      int r = 0;
#pragma unroll
      for (int k = 0; k < 8; k++)
        r += (int)((ang[k] < ang[j]) || ((ang[k] == ang[j]) && (k < j)));
      rk[j] = r;
    }
#pragma unroll
    for (int s = 0; s < 8; s++) {
      float vx = 0.f, vy = 0.f;
#pragma unroll
      for (int j = 0; j < 8; j++) {
        bool sel = (rk[j] == s);
        vx = sel ? ox[j] : vx;
        vy = sel ? oy[j] : vy;
      }
      sbx[s] = vx; sby[s] = vy;
    }
  }

  // ---------------- edges + shoelace areas ---------------------------------
  float eax[8], eay[8], ebx[8], eby[8];
#pragma unroll
  for (int k = 0; k < 8; k++) {
    eax[k] = sax[(k + 1) & 7] - sax[k];
    eay[k] = say[(k + 1) & 7] - say[k];
    ebx[k] = sbx[(k + 1) & 7] - sbx[k];
    eby[k] = sby[(k + 1) & 7] - sby[k];
  }
  float area_a = 0.f, area_b = 0.f;
#pragma unroll
  for (int k = 0; k < 8; k++) {
    area_a += sax[k] * say[(k + 1) & 7] - say[k] * sax[(k + 1) & 7];
    area_b += sbx[k] * sby[(k + 1) & 7] - sby[k] * sbx[(k + 1) & 7];
  }
  area_a *= 0.5f; area_b *= 0.5f;

  // ---------------- candidates: inside vertices + edge intersections -------
  float cxl[40], cyl[40], cal[40];
  int cnt = 0;
  float sumx = 0.f, sumy = 0.f;

#pragma unroll
  for (int j = 0; j < 8; j++) {
    bool all = true;
#pragma unroll
    for (int k = 0; k < 8; k++) {
      float wx = sax[j] - sbx[k], wy = say[j] - sby[k];
      float cr = ebx[k] * wy - eby[k] * wx;
      all = all && (cr >= -1e-6f);
    }
    if (all) { cxl[cnt] = sax[j]; cyl[cnt] = say[j]; sumx += sax[j]; sumy += say[j]; cnt++; }
  }
#pragma unroll
  for (int j = 0; j < 8; j++) {
    bool all = true;
#pragma unroll
    for (int k = 0; k < 8; k++) {
      float wx = sbx[j] - sax[k], wy = sby[j] - say[k];
      float cr = eax[k] * wy - eay[k] * wx;
      all = all && (cr >= -1e-6f);
    }
    if (all) { cxl[cnt] = sbx[j]; cyl[cnt] = sby[j]; sumx += sbx[j]; sumy += sby[j]; cnt++; }
  }
  // division-free accept test; divide only for accepted pairs (~8 of 64)
#pragma unroll
  for (int ii = 0; ii < 8; ii++) {
#pragma unroll
    for (int jj = 0; jj < 8; jj++) {
      float denom = eax[ii] * eby[jj] - eay[ii] * ebx[jj];
      float ad = fabsf(denom);
      float rx = sbx[jj] - sax[ii], ry = sby[jj] - say[ii];
      float nt = rx * eby[jj] - ry * ebx[jj];
      float nu = rx * eay[ii] - ry * eax[ii];
      bool neg = denom < 0.0f;
      float ntA = neg ? -nt : nt;
      float nuA = neg ? -nu : nu;
      bool ok = (ad >= 1e-9f) && (ntA >= 0.0f) && (ntA <= ad) &&
                (nuA >= 0.0f) && (nuA <= ad);
      if (ok) {
        float t = __fdividef(nt, denom);
        float px = sax[ii] + t * eax[ii];
        float py = say[ii] + t * eay[ii];
        cxl[cnt] = px; cyl[cnt] = py; sumx += px; sumy += py; cnt++;
      }
    }
  }

  // ---------------- intersection area: pseudoangle sort about centroid -----
  float inter = 0.0f;
  {
    float cntf = fmaxf((float)cnt, 1.0f);
    float ctrx = sumx / cntf, ctry = sumy / cntf;
    for (int t0 = 0; t0 < cnt; t0++)
      cal[t0] = pangle(cxl[t0] - ctrx, cyl[t0] - ctry);
    for (int s = 1; s < cnt; s++) {
      float ka = cal[s], kx = cxl[s], ky = cyl[s];
      int t = s - 1;
      while (t >= 0 && cal[t] > ka) {
        cal[t + 1] = cal[t]; cxl[t + 1] = cxl[t]; cyl[t + 1] = cyl[t];
        t--;
      }
      cal[t + 1] = ka; cxl[t + 1] = kx; cyl[t + 1] = ky;
    }
    float sh = 0.f;
    for (int t0 = 0; t0 < cnt; t0++) {
      int t1 = (t0 + 1 == cnt) ? 0 : t0 + 1;
      sh += cxl[t0] * cyl[t1] - cyl[t0] * cxl[t1];
    }
    inter = (cnt >= 3) ? fmaxf(0.5f * sh, 0.0f) : 0.0f;
  }

  float uni = area_a + area_b - inter;
  float iou = inter / uni;

  // ---------------- convex hull (gift wrapping, pseudoangle argmin) --------
  // Reload the 16 raw points here (L2-hot) so they weren't live above.
  float ch;
  {
    float hx[16], hy[16];
#pragma unroll
    for (int k = 0; k < 4; k++) {
      float4 q = a4[k];
      hx[2 * k] = q.x; hy[2 * k] = q.y; hx[2 * k + 1] = q.z; hy[2 * k + 1] = q.w;
    }
#pragma unroll
    for (int k = 0; k < 4; k++) {
      float4 q = b4[k];
      hx[8 + 2 * k] = q.x; hy[8 + 2 * k] = q.y;
      hx[8 + 2 * k + 1] = q.z; hy[8 + 2 * k + 1] = q.w;
    }
    int start = 0;
    float cpx = hx[0], cpy = hy[0];
#pragma unroll
    for (int k = 1; k < 16; k++) {
      bool better = (hy[k] < cpy) || ((hy[k] == cpy) && (hx[k] < cpx));
      if (better) { start = k; cpx = hx[k]; cpy = hy[k]; }
    }
    float dx = 1.0f, dy = 0.0f;
    float acc = 0.0f;
    for (int it = 0; it < 16; it++) {
      float best = INF_F;
      int nxt = 0;
      float nx = 0.f, ny = 0.f;
#pragma unroll
      for (int k = 0; k < 16; k++) {
        float vx = hx[k] - cpx, vy = hy[k] - cpy;
        float d2 = vx * vx + vy * vy;
        float c = dx * vy - dy * vx;
        float d = dx * vx + dy * vy;
        float a = pangle2pi(c, d);
        a = (d2 < 1e-16f) ? INF_F : a;
        if (a < best) { best = a; nxt = k; nx = hx[k]; ny = hy[k]; }
      }
      acc += cpx * ny - cpy * nx;
      dx = nx - cpx; dy = ny - cpy;
      cpx = nx; cpy = ny;
      if (nxt == start) break;
    }
    ch = 0.5f * acc;
  }

  float ciou_v = iou - (ch - uni) / ch;

  // ---------------- mean reduction (double, single-kernel finalize) --------
  double v = (double)ciou_v;
#pragma unroll
  for (int o = 16; o > 0; o >>= 1) v += __shfl_down_sync(0xFFFFFFFFu, v, o);
  __shared__ double smem[4];
  int lane = threadIdx.x & 31;
  int wid = threadIdx.x >> 5;
  if (lane == 0) smem[wid] = v;
  __syncthreads();
  if (threadIdx.x == 0) {
    double s = smem[0] + smem[1] + smem[2] + smem[3];
    atomicAdd(&g_acc, s);
    __threadfence();
    unsigned int old = atomicAdd(&g_cnt, 1u);
    if (old == (unsigned int)(NBLOCKS - 1)) {
      double total = atomicAdd(&g_acc, 0.0);
      out[0] = (float)(total * (1.0 / (double)BATCH));
      g_acc = 0.0;
      g_cnt = 0u;
    }
  }
}

extern "C" void kernel_launch(void* const* d_in, const int* in_sizes, int n_in,
                              void* d_out, int out_size) {
  const float* a = (const float*)d_in[0];
  const float* b = (const float*)d_in[1];
  float* out = (float*)d_out;
  ciou_main_kernel<<<NBLOCKS, 128>>>(a, b, out);
}

// round 9
// speedup vs baseline: 1.4842x; 1.2067x over previous
#include <cuda_runtime.h>

#define BATCH 262144
#define NBLOCKS (BATCH / 128)

static __device__ double g_acc = 0.0;
static __device__ unsigned int g_cnt = 0;

// Monotone key equivalent to atan2f(y, x) ordering over (-pi, pi].
__device__ __forceinline__ float pangle(float x, float y) {
  float a = fabsf(x) + fabsf(y);
  float r = (a == 0.0f) ? 1.0f : __fdividef(x, a);
  return (y >= 0.0f) ? (1.0f - r) : (r - 1.0f);
}

__global__ void __launch_bounds__(128, 3) ciou_main_kernel(
    const float* __restrict__ A, const float* __restrict__ Bm,
    float* __restrict__ out) {
  int i = blockIdx.x * blockDim.x + threadIdx.x;
  const float4* a4 = reinterpret_cast<const float4*>(A) + (size_t)i * 4;
  const float4* b4 = reinterpret_cast<const float4*>(Bm) + (size_t)i * 4;

  // ---------------- sort_poly (stable rank sort, pseudoangle keys) ---------
  float sax[8], say[8], sbx[8], sby[8];
  {
    float ox[8], oy[8];
#pragma unroll
    for (int k = 0; k < 4; k++) {
      float4 q = a4[k];
      ox[2 * k] = q.x; oy[2 * k] = q.y; ox[2 * k + 1] = q.z; oy[2 * k + 1] = q.w;
    }
    float cx = 0.f, cy = 0.f;
#pragma unroll
    for (int k = 0; k < 8; k++) { cx += ox[k]; cy += oy[k]; }
    cx *= 0.125f; cy *= 0.125f;
    float ang[8];
#pragma unroll
    for (int k = 0; k < 8; k++) ang[k] = pangle(ox[k] - cx, oy[k] - cy);
    int rk[8];
#pragma unroll
    for (int j = 0; j < 8; j++) {
      int r = 0;
#pragma unroll
      for (int k = 0; k < 8; k++)
        r += (int)((ang[k] < ang[j]) || ((ang[k] == ang[j]) && (k < j)));
      rk[j] = r;
    }
#pragma unroll
    for (int s = 0; s < 8; s++) {
      float vx = 0.f, vy = 0.f;
#pragma unroll
      for (int j = 0; j < 8; j++) {
        bool sel = (rk[j] == s);
        vx = sel ? ox[j] : vx;
        vy = sel ? oy[j] : vy;
      }
      sax[s] = vx; say[s] = vy;
    }
  }
  {
    float ox[8], oy[8];
#pragma unroll
    for (int k = 0; k < 4; k++) {
      float4 q = b4[k];
      ox[2 * k] = q.x; oy[2 * k] = q.y; ox[2 * k + 1] = q.z; oy[2 * k + 1] = q.w;
    }
    float cx = 0.f, cy = 0.f;
#pragma unroll
    for (int k = 0; k < 8; k++) { cx += ox[k]; cy += oy[k]; }
    cx *= 0.125f; cy *= 0.125f;
    float ang[8];
#pragma unroll
    for (int k = 0; k < 8; k++) ang[k] = pangle(ox[k] - cx, oy[k] - cy);
    int rk[8];
#pragma unroll
    for (int j = 0; j < 8; j++) {
      int r = 0;
#pragma unroll
      for (int k = 0; k < 8; k++)
        r += (int)((ang[k] < ang[j]) || ((ang[k] == ang[j]) && (k < j)));
      rk[j] = r;
    }
#pragma unroll
    for (int s = 0; s < 8; s++) {
      float vx = 0.f, vy = 0.f;
#pragma unroll
      for (int j = 0; j < 8; j++) {
        bool sel = (rk[j] == s);
        vx = sel ? ox[j] : vx;
        vy = sel ? oy[j] : vy;
      }
      sbx[s] = vx; sby[s] = vy;
    }
  }

  // ---------------- edges + shoelace areas ---------------------------------
  float eax[8], eay[8], ebx[8], eby[8];
#pragma unroll
  for (int k = 0; k < 8; k++) {
    eax[k] = sax[(k + 1) & 7] - sax[k];
    eay[k] = say[(k + 1) & 7] - say[k];
    ebx[k] = sbx[(k + 1) & 7] - sbx[k];
    eby[k] = sby[(k + 1) & 7] - sby[k];
  }
  float area_a = 0.f, area_b = 0.f;
#pragma unroll
  for (int k = 0; k < 8; k++) {
    area_a += sax[k] * say[(k + 1) & 7] - say[k] * sax[(k + 1) & 7];
    area_b += sbx[k] * sby[(k + 1) & 7] - sby[k] * sbx[(k + 1) & 7];
  }
  area_a *= 0.5f; area_b *= 0.5f;

  // ---------------- candidates: inside vertices + edge intersections -------
  float cxl[40], cyl[40], cal[40];
  int cnt = 0;
  float sumx = 0.f, sumy = 0.f;

#pragma unroll
  for (int j = 0; j < 8; j++) {
    bool all = true;
#pragma unroll
    for (int k = 0; k < 8; k++) {
      float wx = sax[j] - sbx[k], wy = say[j] - sby[k];
      float cr = ebx[k] * wy - eby[k] * wx;
      all = all && (cr >= -1e-6f);
    }
    if (all) { cxl[cnt] = sax[j]; cyl[cnt] = say[j]; sumx += sax[j]; sumy += say[j]; cnt++; }
  }
#pragma unroll
  for (int j = 0; j < 8; j++) {
    bool all = true;
#pragma unroll
    for (int k = 0; k < 8; k++) {
      float wx = sbx[j] - sax[k], wy = sby[j] - say[k];
      float cr = eax[k] * wy - eay[k] * wx;
      all = all && (cr >= -1e-6f);
    }
    if (all) { cxl[cnt] = sbx[j]; cyl[cnt] = sby[j]; sumx += sbx[j]; sumy += sby[j]; cnt++; }
  }
  // division-free accept test; divide only for accepted pairs (~8 of 64)
#pragma unroll
  for (int ii = 0; ii < 8; ii++) {
#pragma unroll
    for (int jj = 0; jj < 8; jj++) {
      float denom = eax[ii] * eby[jj] - eay[ii] * ebx[jj];
      float ad = fabsf(denom);
      float rx = sbx[jj] - sax[ii], ry = sby[jj] - say[ii];
      float nt = rx * eby[jj] - ry * ebx[jj];
      float nu = rx * eay[ii] - ry * eax[ii];
      bool neg = denom < 0.0f;
      float ntA = neg ? -nt : nt;
      float nuA = neg ? -nu : nu;
      bool ok = (ad >= 1e-9f) && (ntA >= 0.0f) && (ntA <= ad) &&
                (nuA >= 0.0f) && (nuA <= ad);
      if (ok) {
        float t = __fdividef(nt, denom);
        float px = sax[ii] + t * eax[ii];
        float py = say[ii] + t * eay[ii];
        cxl[cnt] = px; cyl[cnt] = py; sumx += px; sumy += py; cnt++;
      }
    }
  }

  // ---------------- intersection area: pseudoangle sort about centroid -----
  float inter = 0.0f;
  {
    float cntf = fmaxf((float)cnt, 1.0f);
    float ctrx = sumx / cntf, ctry = sumy / cntf;
    for (int t0 = 0; t0 < cnt; t0++)
      cal[t0] = pangle(cxl[t0] - ctrx, cyl[t0] - ctry);
    for (int s = 1; s < cnt; s++) {
      float ka = cal[s], kx = cxl[s], ky = cyl[s];
      int t = s - 1;
      while (t >= 0 && cal[t] > ka) {
        cal[t + 1] = cal[t]; cxl[t + 1] = cxl[t]; cyl[t + 1] = cyl[t];
        t--;
      }
      cal[t + 1] = ka; cxl[t + 1] = kx; cyl[t + 1] = ky;
    }
    float sh = 0.f;
    for (int t0 = 0; t0 < cnt; t0++) {
      int t1 = (t0 + 1 == cnt) ? 0 : t0 + 1;
      sh += cxl[t0] * cyl[t1] - cyl[t0] * cxl[t1];
    }
    inter = (cnt >= 3) ? fmaxf(0.5f * sh, 0.0f) : 0.0f;
  }

  float uni = area_a + area_b - inter;
  float iou = inter / uni;

  // ---------------- convex hull: cross-product tournament tree -------------
  // Reload the 16 raw points here (L2-hot) so they weren't live above.
  float ch;
  {
    float hx[16], hy[16];
#pragma unroll
    for (int k = 0; k < 4; k++) {
      float4 q = a4[k];
      hx[2 * k] = q.x; hy[2 * k] = q.y; hx[2 * k + 1] = q.z; hy[2 * k + 1] = q.w;
    }
#pragma unroll
    for (int k = 0; k < 4; k++) {
      float4 q = b4[k];
      hx[8 + 2 * k] = q.x; hy[8 + 2 * k] = q.y;
      hx[8 + 2 * k + 1] = q.z; hy[8 + 2 * k + 1] = q.w;
    }
    int start = 0;
    float cpx = hx[0], cpy = hy[0];
#pragma unroll
    for (int k = 1; k < 16; k++) {
      bool better = (hy[k] < cpy) || ((hy[k] == cpy) && (hx[k] < cpx));
      if (better) { start = k; cpx = hx[k]; cpy = hy[k]; }
    }
    float acc = 0.0f;
    for (int it = 0; it < 16; it++) {
      // At a hull vertex all candidate angles (CCW from previous edge) lie in
      // [0, pi], so cross(v_a, v_b) < 0  <=>  b has the smaller angle.
      // Ties (cr==0) go to the lower index = reference first-occurrence argmin.
      float vx[16], vy[16], px[16], py[16];
      bool val[16];
      int widx[16];
#pragma unroll
      for (int k = 0; k < 16; k++) {
        float vxx = hx[k] - cpx, vyy = hy[k] - cpy;
        vx[k] = vxx; vy[k] = vyy;
        px[k] = hx[k]; py[k] = hy[k];
        val[k] = (vxx * vxx + vyy * vyy) >= 1e-16f;
        widx[k] = k;
      }
#pragma unroll
      for (int st = 1; st < 16; st <<= 1) {
#pragma unroll
        for (int a0 = 0; a0 < 16; a0 += 2 * st) {
          int b0 = a0 + st;
          float cr = vx[a0] * vy[b0] - vy[a0] * vx[b0];
          bool bwin = val[b0] && (!val[a0] || (cr < 0.0f));
          vx[a0] = bwin ? vx[b0] : vx[a0];
          vy[a0] = bwin ? vy[b0] : vy[a0];
          px[a0] = bwin ? px[b0] : px[a0];
          py[a0] = bwin ? py[b0] : py[a0];
          widx[a0] = bwin ? widx[b0] : widx[a0];
          val[a0] = val[a0] || val[b0];
        }
      }
      acc += cpx * py[0] - cpy * px[0];
      cpx = px[0]; cpy = py[0];
      if (widx[0] == start) break;
    }
    ch = 0.5f * acc;
  }

  float ciou_v = iou - (ch - uni) / ch;

  // ---------------- mean reduction (double, single-kernel finalize) --------
  double v = (double)ciou_v;
#pragma unroll
  for (int o = 16; o > 0; o >>= 1) v += __shfl_down_sync(0xFFFFFFFFu, v, o);
  __shared__ double smem[4];
  int lane = threadIdx.x & 31;
  int wid = threadIdx.x >> 5;
  if (lane == 0) smem[wid] = v;
  __syncthreads();
  if (threadIdx.x == 0) {
    double s = smem[0] + smem[1] + smem[2] + smem[3];
    atomicAdd(&g_acc, s);
    __threadfence();
    unsigned int old = atomicAdd(&g_cnt, 1u);
    if (old == (unsigned int)(NBLOCKS - 1)) {
      double total = atomicAdd(&g_acc, 0.0);
      out[0] = (float)(total * (1.0 / (double)BATCH));
      g_acc = 0.0;
      g_cnt = 0u;
    }
  }
}

extern "C" void kernel_launch(void* const* d_in, const int* in_sizes, int n_in,
                              void* d_out, int out_size) {
  const float* a = (const float*)d_in[0];
  const float* b = (const float*)d_in[1];
  float* out = (float*)d_out;
  ciou_main_kernel<<<NBLOCKS, 128>>>(a, b, out);
}